// round 3
// baseline (speedup 1.0000x reference)
#include <cuda_runtime.h>
#include <cuda_fp16.h>
#include <cstdint>

// ---------------- problem constants ----------------
#define KTOT   3072
#define NOUT   12288
#define MB     64            // batch (GEMM N side)
#define MTILE  128           // output rows per CTA (GEMM M side)
#define KC     64            // K per chunk
#define NCHUNK (KTOT / KC)   // 48
#define NTH    256
#define NCTA   (NOUT / MTILE) // 96

// smem: A stages 2 x (128 rows x 128B) ; B stages 2 x (64 rows x 128B)
#define A_ST(s) ((unsigned)(s) * 16384u)
#define B_ST(s) (32768u + (unsigned)(s) * 8192u)
#define SMEM_TOTAL 49152

// x pre-converted to fp16 (k-major, [64][3072])
__device__ __align__(16) __half g_xh[MB * KTOT];

__global__ void xconv_kernel(const float* __restrict__ x) {
    int i = blockIdx.x * blockDim.x + threadIdx.x;   // indexes float4
    float4 v = ((const float4*)x)[i];
    __half2 h0 = __floats2half2_rn(v.x, v.y);
    __half2 h1 = __floats2half2_rn(v.z, v.w);
    uint2 r;
    r.x = *reinterpret_cast<uint32_t*>(&h0);
    r.y = *reinterpret_cast<uint32_t*>(&h1);
    ((uint2*)g_xh)[i] = r;
}

// ---------------- device helpers ----------------
__device__ __forceinline__ uint32_t smem_u32(const void* p) {
    uint32_t a;
    asm("{ .reg .u64 t; cvta.to.shared.u64 t, %1; cvt.u32.u64 %0, t; }" : "=r"(a) : "l"(p));
    return a;
}
__device__ __forceinline__ uint32_t swz(uint32_t off) {  // SW128 Swizzle<3,4,3>
    return off ^ ((off >> 3) & 0x70u);
}
__device__ __forceinline__ void sts64(uint32_t addr, uint32_t a, uint32_t b) {
    asm volatile("st.shared.v2.b32 [%0], {%1, %2};" :: "r"(addr), "r"(a), "r"(b) : "memory");
}
__device__ __forceinline__ void sts128(uint32_t addr, uint4 v) {
    asm volatile("st.shared.v4.b32 [%0], {%1, %2, %3, %4};"
                 :: "r"(addr), "r"(v.x), "r"(v.y), "r"(v.z), "r"(v.w) : "memory");
}
__device__ __forceinline__ void ldsm4(uint32_t& r0, uint32_t& r1, uint32_t& r2, uint32_t& r3,
                                      uint32_t addr) {
    asm volatile("ldmatrix.sync.aligned.m8n8.x4.shared.b16 {%0,%1,%2,%3}, [%4];"
                 : "=r"(r0), "=r"(r1), "=r"(r2), "=r"(r3) : "r"(addr));
}
__device__ __forceinline__ void mma16816(float& c0, float& c1, float& c2, float& c3,
                                         uint32_t a0, uint32_t a1, uint32_t a2, uint32_t a3,
                                         uint32_t b0, uint32_t b1) {
    asm volatile(
        "mma.sync.aligned.m16n8k16.row.col.f32.f16.f16.f32 "
        "{%0,%1,%2,%3}, {%4,%5,%6,%7}, {%8,%9}, {%0,%1,%2,%3};"
        : "+f"(c0), "+f"(c1), "+f"(c2), "+f"(c3)
        : "r"(a0), "r"(a1), "r"(a2), "r"(a3), "r"(b0), "r"(b1));
}
// dequant 4 int32 codes -> 4 fp16 halves (2 regs): (code - 128) * s
__device__ __forceinline__ uint2 dq4(int4 cd, float s) {
    const float o = -128.0f * s;
    float f0 = fmaf((float)cd.x, s, o);
    float f1 = fmaf((float)cd.y, s, o);
    float f2 = fmaf((float)cd.z, s, o);
    float f3 = fmaf((float)cd.w, s, o);
    __half2 h0 = __floats2half2_rn(f0, f1);
    __half2 h1 = __floats2half2_rn(f2, f3);
    uint2 r;
    r.x = *reinterpret_cast<uint32_t*>(&h0);
    r.y = *reinterpret_cast<uint32_t*>(&h1);
    return r;
}

__global__ __launch_bounds__(NTH, 1)
void dql_kernel(const int*   __restrict__ wq,
                const float* __restrict__ ws,
                const int*   __restrict__ bq,
                const float* __restrict__ bs,
                float*       __restrict__ out) {
    extern __shared__ __align__(1024) char smem[];
    const uint32_t sb = smem_u32(smem);

    const int tid  = threadIdx.x;
    const int lane = tid & 31;
    const int wid  = tid >> 5;
    const int wm   = wid & 3;   // warp M index (4)
    const int wn   = wid >> 2;  // warp N index (2)
    const int cta  = blockIdx.x;

    // ---- A (weights) gmem->reg mapping: 8 lanes cover one contiguous 128B ----
    const int a_sub = tid & 7;   // 16B segment within 128B
    const int a_r0  = tid >> 3;  // base row 0..31; rows a_r0 + 32*rr
    const int4*   a_base  = (const int4*)(wq + (size_t)(cta * MTILE) * KTOT);
    const float2* ws_base = (const float2*)(ws + (size_t)(cta * MTILE) * (KTOT / 32));

    // ---- B (x fp16) gmem->reg mapping ----
    const uint4* x_base = (const uint4*)g_xh;  // 8 halves per uint4

    int4   areg[8];
    float2 sreg[4];
    uint4  xreg[2];

    // ldmatrix lane address offsets (byte offsets within a stage tile)
    const int a_row    = wm * 32 + (lane & 15);
    const int a_colsel = (lane >> 4) & 1;
    const int b_row    = wn * 32 + (lane & 7) + (((lane >> 4) & 1) << 3);
    const int b_colsel = (lane >> 3) & 1;

    float acc[2][4][4];
#pragma unroll
    for (int t = 0; t < 2; t++)
#pragma unroll
        for (int nf = 0; nf < 4; nf++)
#pragma unroll
            for (int i = 0; i < 4; i++) acc[t][nf][i] = 0.0f;

    // -------- g2r for chunk c --------
    auto g2r = [&](int c) {
#pragma unroll
        for (int rr = 0; rr < 4; rr++) {
            const int r = a_r0 + rr * 32;
            const size_t base = (size_t)r * (KTOT / 4) + c * 16 + a_sub;
            areg[rr * 2 + 0] = a_base[base];
            areg[rr * 2 + 1] = a_base[base + 8];
            sreg[rr] = ws_base[r * (KTOT / 64) + c];
        }
#pragma unroll
        for (int nn = 0; nn < 2; nn++) {
            const int n = (tid >> 3) + nn * 32;
            xreg[nn] = x_base[((size_t)n * KTOT + c * KC) / 8 + a_sub];
        }
    };

    // -------- r2s (dequant + store) into stage st --------
    auto r2s = [&](int st) {
        const uint32_t As = sb + A_ST(st);
        const uint32_t Bs = sb + B_ST(st);
#pragma unroll
        for (int rr = 0; rr < 4; rr++) {
            const int r = a_r0 + rr * 32;
            uint2 d0 = dq4(areg[rr * 2 + 0], sreg[rr].x);
            uint2 d1 = dq4(areg[rr * 2 + 1], sreg[rr].y);
            sts64(As + swz((uint32_t)(r * 128 + a_sub * 8)),      d0.x, d0.y);
            sts64(As + swz((uint32_t)(r * 128 + 64 + a_sub * 8)), d1.x, d1.y);
        }
#pragma unroll
        for (int nn = 0; nn < 2; nn++) {
            const int n = (tid >> 3) + nn * 32;
            sts128(Bs + swz((uint32_t)(n * 128 + a_sub * 16)), xreg[nn]);
        }
    };

    // -------- compute on stage st --------
    auto compute = [&](int st) {
        const uint32_t As = sb + A_ST(st);
        const uint32_t Bs = sb + B_ST(st);
#pragma unroll
        for (int ks = 0; ks < 4; ks++) {
            uint32_t a[2][4], b[2][4];
#pragma unroll
            for (int t = 0; t < 2; t++) {
                uint32_t addr = As + swz((uint32_t)((a_row + t * 16) * 128 +
                                                    ks * 32 + a_colsel * 16));
                ldsm4(a[t][0], a[t][1], a[t][2], a[t][3], addr);
            }
#pragma unroll
            for (int u = 0; u < 2; u++) {
                uint32_t addr = Bs + swz((uint32_t)((b_row + u * 16) * 128 +
                                                    ks * 32 + b_colsel * 16));
                ldsm4(b[u][0], b[u][1], b[u][2], b[u][3], addr);
            }
#pragma unroll
            for (int t = 0; t < 2; t++) {
#pragma unroll
                for (int nf = 0; nf < 4; nf++) {
                    const int u = nf >> 1;
                    const int p = (nf & 1) * 2;
                    mma16816(acc[t][nf][0], acc[t][nf][1], acc[t][nf][2], acc[t][nf][3],
                             a[t][0], a[t][1], a[t][2], a[t][3],
                             b[u][p], b[u][p + 1]);
                }
            }
        }
    };

    // -------- pipeline --------
    g2r(0);
    r2s(0);
    __syncthreads();
    for (int c = 0; c < NCHUNK; c++) {
        if (c + 1 < NCHUNK) g2r(c + 1);
        compute(c & 1);
        if (c + 1 < NCHUNK) r2s((c + 1) & 1);
        __syncthreads();
    }

    // -------- epilogue: bias + store --------
    const int g   = lane >> 2;
    const int tig = lane & 3;
    const int ob  = cta * MTILE + wm * 32 + g;
    float bias[2][2];
#pragma unroll
    for (int t = 0; t < 2; t++)
#pragma unroll
        for (int hh = 0; hh < 2; hh++) {
            const int o = ob + t * 16 + hh * 8;
            bias[t][hh] = ((float)bq[o] - 128.0f) * bs[o >> 5];
        }

#pragma unroll
    for (int t = 0; t < 2; t++) {
        const int o0 = ob + t * 16;
#pragma unroll
        for (int nf = 0; nf < 4; nf++) {
            const int mc = wn * 32 + nf * 8 + tig * 2;
            out[(size_t)mc * NOUT + o0]           = acc[t][nf][0] + bias[t][0];
            out[(size_t)(mc + 1) * NOUT + o0]     = acc[t][nf][1] + bias[t][0];
            out[(size_t)mc * NOUT + o0 + 8]       = acc[t][nf][2] + bias[t][1];
            out[(size_t)(mc + 1) * NOUT + o0 + 8] = acc[t][nf][3] + bias[t][1];
        }
    }
}

extern "C" void kernel_launch(void* const* d_in, const int* in_sizes, int n_in,
                              void* d_out, int out_size) {
    (void)in_sizes; (void)n_in; (void)out_size;
    xconv_kernel<<<(MB * KTOT / 4 + NTH - 1) / NTH, NTH>>>((const float*)d_in[0]);
    cudaFuncSetAttribute(dql_kernel, cudaFuncAttributeMaxDynamicSharedMemorySize, SMEM_TOTAL);
    dql_kernel<<<NCTA, NTH, SMEM_TOTAL>>>(
        (const int*)d_in[1],     // w_q
        (const float*)d_in[2],   // w_scales
        (const int*)d_in[3],     // b_q
        (const float*)d_in[4],   // b_scales
        (float*)d_out);
}